// round 16
// baseline (speedup 1.0000x reference)
#include <cuda_runtime.h>
#include <cuda_fp16.h>
#include <cstdint>

// ---------------------------------------------------------------------------
// MADPSNet via mma.sync fp16 single-pass GEMMs, v10.
//   v10: big warp tile. Evidence (R13-R15): tensor% tracks the MMA:ldsm
//   issue ratio (2-pass=53%, 1-pass=36%); LDS bandwidth/barriers were NOT
//   binding. Warp tile 64x64 -> 8 ldsm feed 32 independent MMAs per ks
//   (ratio 80%). CTA 256x128, 8 warps (4m x 2n), BK=64, 3-stage cp.async,
//   ~180 regs -> 1 CTA/SM (8 warps, deliberate: MMA-dense streams).
//   Numerics unchanged: fp16 x fp16 -> fp32 acc (rel_err 5.75e-4).
// ---------------------------------------------------------------------------

#define NUM_AGENTS 8
#define BATCH      2048
typedef __half f16;

// ---------------- scratch (__device__ globals) ----------------------------
__device__ f16 g_inq[NUM_AGENTS * BATCH * 256];     // fp16 input
__device__ f16 g_y1[NUM_AGENTS * BATCH * 512];      // fp16 activations
__device__ f16 g_y2[NUM_AGENTS * BATCH * 256];
__device__ f16 g_y3[NUM_AGENTS * BATCH * 512];
__device__ float g_p4[2 * NUM_AGENTS * BATCH * 128];   // L4 split-K partials

__device__ f16 g_w1[NUM_AGENTS * 256 * 512];
__device__ f16 g_w2[NUM_AGENTS * 512 * 256];
__device__ f16 g_w3[NUM_AGENTS * 256 * 512];
__device__ f16 g_w4[NUM_AGENTS * 512 * 128];

// ---------------- helpers --------------------------------------------------
__device__ __forceinline__ uint32_t smem_u32(const void* p) {
    uint32_t a;
    asm("{ .reg .u64 t; cvta.to.shared.u64 t, %1; cvt.u32.u64 %0, t; }" : "=r"(a) : "l"(p));
    return a;
}
__device__ __forceinline__ void ldsm4(uint32_t (&r)[4], uint32_t addr) {
    asm volatile("ldmatrix.sync.aligned.m8n8.x4.shared.b16 {%0,%1,%2,%3}, [%4];"
                 : "=r"(r[0]), "=r"(r[1]), "=r"(r[2]), "=r"(r[3]) : "r"(addr));
}
__device__ __forceinline__ void ldsm4t(uint32_t (&r)[4], uint32_t addr) {
    asm volatile("ldmatrix.sync.aligned.m8n8.x4.trans.shared.b16 {%0,%1,%2,%3}, [%4];"
                 : "=r"(r[0]), "=r"(r[1]), "=r"(r[2]), "=r"(r[3]) : "r"(addr));
}
__device__ __forceinline__ void mma_f16(float (&d)[4], const uint32_t (&a)[4],
                                        uint32_t b0, uint32_t b1) {
    asm volatile(
        "mma.sync.aligned.m16n8k16.row.col.f32.f16.f16.f32 "
        "{%0,%1,%2,%3}, {%4,%5,%6,%7}, {%8,%9}, {%0,%1,%2,%3};"
        : "+f"(d[0]), "+f"(d[1]), "+f"(d[2]), "+f"(d[3])
        : "r"(a[0]), "r"(a[1]), "r"(a[2]), "r"(a[3]), "r"(b0), "r"(b1));
}
__device__ __forceinline__ void cp16(uint32_t dst, const void* src) {
    asm volatile("cp.async.cg.shared.global [%0], [%1], 16;" :: "r"(dst), "l"(src));
}
template <int NW>
__device__ __forceinline__ void cp_wait() {
    asm volatile("cp.async.wait_group %0;" :: "n"(NW));
}
#define CP_COMMIT() asm volatile("cp.async.commit_group;" ::: "memory")

__device__ __forceinline__ uint32_t pack2h(float a, float b) {
    __half2 t = __floats2half2_rn(a, b);
    return *reinterpret_cast<uint32_t*>(&t);
}

// ---------------- fused prepass: fp32 -> fp16 conversions ------------------
__global__ void __launch_bounds__(256)
prep_kernel(const float* __restrict__ Ws1, const float* __restrict__ Ws2,
            const float* __restrict__ Wd1, const float* __restrict__ Wd2,
            const float* __restrict__ inputs,
            const int* __restrict__ sel_s, const int* __restrict__ sel_d,
            f16* __restrict__ w1, f16* __restrict__ w2,
            f16* __restrict__ w3, f16* __restrict__ w4,
            f16* __restrict__ inq)
{
    const int seg = blockIdx.y;
    const int ag  = blockIdx.z;
    const float* src;
    f16* oq;
    int n4;
    int e;
    switch (seg) {
    case 0:
        e = sel_s[ag]; e = e < 0 ? 0 : (e > 7 ? 7 : e);
        src = Ws1 + (size_t)e * 131072; oq = w1 + (size_t)ag * 131072;
        n4 = 32768; break;
    case 1:
        e = sel_s[ag]; e = e < 0 ? 0 : (e > 7 ? 7 : e);
        src = Ws2 + (size_t)e * 131072; oq = w2 + (size_t)ag * 131072;
        n4 = 32768; break;
    case 2:
        e = sel_d[ag]; e = e < 0 ? 0 : (e > 7 ? 7 : e);
        src = Wd1 + (size_t)e * 131072; oq = w3 + (size_t)ag * 131072;
        n4 = 32768; break;
    case 3:
        e = sel_d[ag]; e = e < 0 ? 0 : (e > 7 ? 7 : e);
        src = Wd2 + (size_t)e * 65536;  oq = w4 + (size_t)ag * 65536;
        n4 = 16384; break;
    default:
        src = inputs + (size_t)ag * 524288; oq = inq + (size_t)ag * 524288;
        n4 = 131072; break;
    }
    for (int i = blockIdx.x * 256 + threadIdx.x; i < n4; i += 32 * 256) {
        float4 v = ((const float4*)src)[i];
        ((uint2*)oq)[i] = make_uint2(pack2h(v.x, v.y), pack2h(v.z, v.w));
    }
}

// ---------------- main GEMM ------------------------------------------------
// CTA tile 256m x 128n, 8 warps (4m x 2n, warp tile 64m x 64n), BK=64,
// 3-stage cp.async. Stage: A 32KB (256 rows x 128B swz) | B 16KB (64 k-rows
// x 256B swz) = 48KB. Single fp16 MMA pass; 32 independent MMAs per ks.
// OMODE: 0 = fp32 out + bias, 1 = fp16 out + bias, 2 = raw fp32 partial.
// K = per-k-group depth, KROW = full A row stride (weight per-agent stride
// is KROW*N). blockIdx.x encodes (kgroup, n-tile): kg = bx/(N/128).
template <int K, int KROW, int N, bool RELU, int OMODE>
__global__ void __launch_bounds__(256, 1)
gemm_mma_kernel(const f16* __restrict__ A_,
                const f16* __restrict__ W_,
                const float* __restrict__ Ball,
                float* __restrict__ Out,
                f16* __restrict__ Oq,
                const int* __restrict__ sel)
{
    extern __shared__ __align__(1024) char smem[];
    const uint32_t sb = smem_u32(smem);

    const int tid  = threadIdx.x;
    const int wid  = tid >> 5;
    const int lane = tid & 31;

    const int ag = blockIdx.z;
    int e = sel[ag]; e = e < 0 ? 0 : (e > 7 ? 7 : e);

    const int NX = N / 128;
    const int kg = blockIdx.x / NX;
    const int bn = (blockIdx.x % NX) * 128;
    const int bm = blockIdx.y * 256;

    const f16* Ap = A_ + (size_t)ag * BATCH * KROW + (size_t)kg * K;
    const f16* Bp = W_ + (size_t)ag * KROW * N + (size_t)kg * K * N;
    const float* bp = Ball + (size_t)e * N;

    // smem: [0..512) bias fp32, [1024..) 3 x 48KB stage buffers
    if (OMODE != 2 && tid < 128) ((float*)smem)[tid] = bp[bn + tid];

    const int m0 = (wid >> 1) * 64;   // 4 m-warps
    const int n0 = (wid & 1) * 64;    // 2 n-warps

    // A ldsm bases (4 m-frags of 16 rows): row r, chunk = ks*2 + (lane>>4),
    // swizzled ((chunk ^ (r&7))<<4); ks applied by XOR (ks<<5).
    const int lrow = lane & 15, lqh = lane >> 4;
    uint32_t aA[4];
#pragma unroll
    for (int mt = 0; mt < 4; mt++) {
        int r = m0 + mt * 16 + lrow;
        aA[mt] = sb + 1024 + (uint32_t)(r * 128 + ((lqh ^ (r & 7)) << 4));
    }
    // B (trans) bases (4 n-groups of 16): k-row kr, 16B n-chunk nch; +ks*4096.
    const int kr = (lane & 7) + ((lane >> 3) & 1) * 8;
    uint32_t bB[4];
#pragma unroll
    for (int g = 0; g < 4; g++) {
        int nch = ((n0 + g * 16) >> 3) + (lane >> 4);
        bB[g] = sb + 1024 + 32768 + (uint32_t)(kr * 256 + ((nch ^ (kr & 7)) << 4));
    }

    float acc[4][8][4];
#pragma unroll
    for (int mt = 0; mt < 4; mt++)
#pragma unroll
        for (int nt = 0; nt < 8; nt++)
#pragma unroll
            for (int j = 0; j < 4; j++) acc[mt][nt][j] = 0.0f;

    const int NC = K / 64;

    auto ISSUE = [&](int c) {
        const int k0 = c * 64;
        const uint32_t s = sb + 1024 + (uint32_t)(c % 3) * 49152u;
        // A: 256 rows x 8 chunks(16B) = 2048; 8/thread
#pragma unroll
        for (int i = 0; i < 8; i++) {
            int fid = i * 256 + tid;
            int r = fid >> 3, cq = fid & 7;
            size_t go = (size_t)(bm + r) * KROW + k0 + cq * 8;
            cp16(s + (uint32_t)(r * 128 + ((cq ^ (r & 7)) << 4)), Ap + go);
        }
        // B: 64 k-rows x 16 chunks(16B) = 1024; 4/thread
#pragma unroll
        for (int i = 0; i < 4; i++) {
            int fid = i * 256 + tid;
            int r = fid >> 4, cq = fid & 15;
            size_t go = (size_t)(k0 + r) * N + bn + cq * 8;
            cp16(s + 32768 + (uint32_t)(r * 256 + ((cq ^ (r & 7)) << 4)), Bp + go);
        }
        CP_COMMIT();
    };

    ISSUE(0);
    ISSUE(1);

    for (int c = 0; c < NC; c++) {
        if (c + 1 < NC) cp_wait<1>(); else cp_wait<0>();
        __syncthreads();
        if (c + 2 < NC) ISSUE(c + 2);

        const uint32_t stg = (uint32_t)(c % 3) * 49152u;
#pragma unroll
        for (int ks = 0; ks < 4; ks++) {
            uint32_t ah[4][4];
#pragma unroll
            for (int mt = 0; mt < 4; mt++)
                ldsm4(ah[mt], (aA[mt] + stg) ^ ((uint32_t)ks << 5));
#pragma unroll
            for (int g = 0; g < 4; g++) {
                uint32_t b[4];
                ldsm4t(b, bB[g] + stg + (uint32_t)ks * 4096u);
#pragma unroll
                for (int mt = 0; mt < 4; mt++) {
                    const int nt = g * 2;
                    mma_f16(acc[mt][nt],     ah[mt], b[0], b[1]);
                    mma_f16(acc[mt][nt + 1], ah[mt], b[2], b[3]);
                }
            }
        }
    }

    // ---- epilogue: warp covers rows m0..m0+63, cols n0..n0+63 ----
    const float* bias = (const float*)smem;
    float* Cp  = (OMODE == 0) ? (Out + (size_t)ag * BATCH * N) : nullptr;
    float* Pp  = (OMODE == 2) ? (Out + ((size_t)kg * NUM_AGENTS + ag) * BATCH * N) : nullptr;
    f16*   OqP = (OMODE == 1) ? (Oq + (size_t)ag * BATCH * N) : nullptr;

#pragma unroll
    for (int mt = 0; mt < 4; mt++) {
        const int mrow = bm + m0 + mt * 16 + (lane >> 2);
#pragma unroll
        for (int nt = 0; nt < 8; nt++) {
            const int nc = n0 + nt * 8 + 2 * (lane & 3);
            float o0 = acc[mt][nt][0], o1 = acc[mt][nt][1];
            float o2 = acc[mt][nt][2], o3 = acc[mt][nt][3];
            if (OMODE != 2) {
                const float b0 = bias[nc], b1 = bias[nc + 1];
                o0 += b0; o1 += b1; o2 += b0; o3 += b1;
            }
            if (RELU) {
                o0 = fmaxf(o0, 0.f); o1 = fmaxf(o1, 0.f);
                o2 = fmaxf(o2, 0.f); o3 = fmaxf(o3, 0.f);
            }
            const size_t i0 = (size_t)mrow * N + bn + nc;
            const size_t i1 = (size_t)(mrow + 8) * N + bn + nc;
            if (OMODE == 1) {
                *(uint32_t*)(OqP + i0) = pack2h(o0, o1);
                *(uint32_t*)(OqP + i1) = pack2h(o2, o3);
            } else if (OMODE == 0) {
                *(float2*)(Cp + i0) = make_float2(o0, o1);
                *(float2*)(Cp + i1) = make_float2(o2, o3);
            } else {
                *(float2*)(Pp + i0) = make_float2(o0, o1);
                *(float2*)(Pp + i1) = make_float2(o2, o3);
            }
        }
    }
}

// ---------------- split-K reduce: out = p0 + p1 + bias ---------------------
__global__ void __launch_bounds__(256)
reduce4_kernel(const float* __restrict__ P, const float* __restrict__ Ball,
               const int* __restrict__ sel_d, float* __restrict__ out)
{
    const int i = blockIdx.x * 256 + threadIdx.x;          // float4 index
    const float4 a = ((const float4*)P)[i];
    const float4 b = ((const float4*)P)[i + 524288];
    const int e4 = i * 4;
    const int ag = e4 >> 18;                               // / (2048*128)
    int e = sel_d[ag]; e = e < 0 ? 0 : (e > 7 ? 7 : e);
    const float4 bb = *(const float4*)(Ball + e * 128 + (e4 & 127));
    ((float4*)out)[i] = make_float4(a.x + b.x + bb.x, a.y + b.y + bb.y,
                                    a.z + b.z + bb.z, a.w + b.w + bb.w);
}

// ---------------------------------------------------------------------------
extern "C" void kernel_launch(void* const* d_in, const int* in_sizes, int n_in,
                              void* d_out, int out_size)
{
    const float* inputs = (const float*)d_in[0];
    const int*   sel_s  = (const int*)d_in[1];
    const int*   sel_d  = (const int*)d_in[2];
    const float* Ws1 = (const float*)d_in[3];
    const float* bs1 = (const float*)d_in[4];
    const float* Ws2 = (const float*)d_in[5];
    const float* bs2 = (const float*)d_in[6];
    const float* Wd1 = (const float*)d_in[7];
    const float* bd1 = (const float*)d_in[8];
    const float* Wd2 = (const float*)d_in[9];
    const float* bd2 = (const float*)d_in[10];
    float* out = (float*)d_out;

    void* p;
    f16 *inq, *y1, *y2, *y3, *w1, *w2, *w3, *w4;
    float* p4;
    cudaGetSymbolAddress(&p, g_inq); inq = (f16*)p;
    cudaGetSymbolAddress(&p, g_y1);  y1  = (f16*)p;
    cudaGetSymbolAddress(&p, g_y2);  y2  = (f16*)p;
    cudaGetSymbolAddress(&p, g_y3);  y3  = (f16*)p;
    cudaGetSymbolAddress(&p, g_p4);  p4  = (float*)p;
    cudaGetSymbolAddress(&p, g_w1);  w1  = (f16*)p;
    cudaGetSymbolAddress(&p, g_w2);  w2  = (f16*)p;
    cudaGetSymbolAddress(&p, g_w3);  w3  = (f16*)p;
    cudaGetSymbolAddress(&p, g_w4);  w4  = (f16*)p;

    const int SMEM_BYTES = 1024 + 3 * 49152;   // 148480
    // Three distinct instantiations (L1 and L3 share one); each needs opt-in.
    cudaFuncSetAttribute(gemm_mma_kernel<256, 256, 512, true,  1>,
                         cudaFuncAttributeMaxDynamicSharedMemorySize, SMEM_BYTES);
    cudaFuncSetAttribute(gemm_mma_kernel<512, 512, 256, true,  1>,
                         cudaFuncAttributeMaxDynamicSharedMemorySize, SMEM_BYTES);
    cudaFuncSetAttribute(gemm_mma_kernel<256, 512, 128, false, 2>,
                         cudaFuncAttributeMaxDynamicSharedMemorySize, SMEM_BYTES);

    prep_kernel<<<dim3(32, 5, 8), 256>>>(Ws1, Ws2, Wd1, Wd2, inputs, sel_s, sel_d,
                                         w1, w2, w3, w4, inq);

    dim3 blk(256);
    // M-tile = 256 rows -> y = 8
    gemm_mma_kernel<256, 256, 512, true,  1><<<dim3(4, 8, 8), blk, SMEM_BYTES>>>(
        inq, w1, bs1, nullptr, y1, sel_s);
    gemm_mma_kernel<512, 512, 256, true,  1><<<dim3(2, 8, 8), blk, SMEM_BYTES>>>(
        y1, w2, bs2, nullptr, y2, sel_s);
    gemm_mma_kernel<256, 256, 512, true,  1><<<dim3(4, 8, 8), blk, SMEM_BYTES>>>(
        y2, w3, bd1, nullptr, y3, sel_d);
    // L4: split-K x2 -> raw partials, then deterministic reduce (+bias)
    gemm_mma_kernel<256, 512, 128, false, 2><<<dim3(2, 8, 8), blk, SMEM_BYTES>>>(
        y3, w4, bd2, p4, nullptr, sel_d);
    reduce4_kernel<<<2048, 256>>>(p4, bd2, sel_d, out);
}

// round 17
// speedup vs baseline: 1.1053x; 1.1053x over previous
#include <cuda_runtime.h>
#include <cuda_fp16.h>
#include <cstdint>

// ---------------------------------------------------------------------------
// MADPSNet via mma.sync fp16 single-pass GEMMs, v11.
//   v11 = v9 (best passing config: CTA 128x128, warp 32x64, BK=64, 2 CTA/SM,
//   3-stage cp.async) + FULLY UNROLLED chunk loop: NC known at compile time,
//   stage offsets become immediates, c%3 ALU chain deleted, ptxas gets a
//   straight-line window to interleave next-chunk cp.async with MMAs.
//   Numerics unchanged: fp16 x fp16 -> fp32 acc (rel_err 5.75e-4).
// ---------------------------------------------------------------------------

#define NUM_AGENTS 8
#define BATCH      2048
typedef __half f16;

// ---------------- scratch (__device__ globals) ----------------------------
__device__ f16 g_inq[NUM_AGENTS * BATCH * 256];
__device__ f16 g_y1[NUM_AGENTS * BATCH * 512];
__device__ f16 g_y2[NUM_AGENTS * BATCH * 256];
__device__ f16 g_y3[NUM_AGENTS * BATCH * 512];
__device__ float g_p4[2 * NUM_AGENTS * BATCH * 128];   // L4 split-K partials

__device__ f16 g_w1[NUM_AGENTS * 256 * 512];
__device__ f16 g_w2[NUM_AGENTS * 512 * 256];
__device__ f16 g_w3[NUM_AGENTS * 256 * 512];
__device__ f16 g_w4[NUM_AGENTS * 512 * 128];

// ---------------- helpers --------------------------------------------------
__device__ __forceinline__ uint32_t smem_u32(const void* p) {
    uint32_t a;
    asm("{ .reg .u64 t; cvta.to.shared.u64 t, %1; cvt.u32.u64 %0, t; }" : "=r"(a) : "l"(p));
    return a;
}
__device__ __forceinline__ void ldsm4(uint32_t (&r)[4], uint32_t addr) {
    asm volatile("ldmatrix.sync.aligned.m8n8.x4.shared.b16 {%0,%1,%2,%3}, [%4];"
                 : "=r"(r[0]), "=r"(r[1]), "=r"(r[2]), "=r"(r[3]) : "r"(addr));
}
__device__ __forceinline__ void ldsm4t(uint32_t (&r)[4], uint32_t addr) {
    asm volatile("ldmatrix.sync.aligned.m8n8.x4.trans.shared.b16 {%0,%1,%2,%3}, [%4];"
                 : "=r"(r[0]), "=r"(r[1]), "=r"(r[2]), "=r"(r[3]) : "r"(addr));
}
__device__ __forceinline__ void mma_f16(float (&d)[4], const uint32_t (&a)[4],
                                        uint32_t b0, uint32_t b1) {
    asm volatile(
        "mma.sync.aligned.m16n8k16.row.col.f32.f16.f16.f32 "
        "{%0,%1,%2,%3}, {%4,%5,%6,%7}, {%8,%9}, {%0,%1,%2,%3};"
        : "+f"(d[0]), "+f"(d[1]), "+f"(d[2]), "+f"(d[3])
        : "r"(a[0]), "r"(a[1]), "r"(a[2]), "r"(a[3]), "r"(b0), "r"(b1));
}
__device__ __forceinline__ void cp16(uint32_t dst, const void* src) {
    asm volatile("cp.async.cg.shared.global [%0], [%1], 16;" :: "r"(dst), "l"(src));
}
template <int NW>
__device__ __forceinline__ void cp_wait() {
    asm volatile("cp.async.wait_group %0;" :: "n"(NW));
}
#define CP_COMMIT() asm volatile("cp.async.commit_group;" ::: "memory")

__device__ __forceinline__ uint32_t pack2h(float a, float b) {
    __half2 t = __floats2half2_rn(a, b);
    return *reinterpret_cast<uint32_t*>(&t);
}

// ---------------- fused prepass: fp32 -> fp16 conversions ------------------
__global__ void __launch_bounds__(256)
prep_kernel(const float* __restrict__ Ws1, const float* __restrict__ Ws2,
            const float* __restrict__ Wd1, const float* __restrict__ Wd2,
            const float* __restrict__ inputs,
            const int* __restrict__ sel_s, const int* __restrict__ sel_d,
            f16* __restrict__ w1, f16* __restrict__ w2,
            f16* __restrict__ w3, f16* __restrict__ w4,
            f16* __restrict__ inq)
{
    const int seg = blockIdx.y;
    const int ag  = blockIdx.z;
    const float* src;
    f16* oq;
    int n4;
    int e;
    switch (seg) {
    case 0:
        e = sel_s[ag]; e = e < 0 ? 0 : (e > 7 ? 7 : e);
        src = Ws1 + (size_t)e * 131072; oq = w1 + (size_t)ag * 131072;
        n4 = 32768; break;
    case 1:
        e = sel_s[ag]; e = e < 0 ? 0 : (e > 7 ? 7 : e);
        src = Ws2 + (size_t)e * 131072; oq = w2 + (size_t)ag * 131072;
        n4 = 32768; break;
    case 2:
        e = sel_d[ag]; e = e < 0 ? 0 : (e > 7 ? 7 : e);
        src = Wd1 + (size_t)e * 131072; oq = w3 + (size_t)ag * 131072;
        n4 = 32768; break;
    case 3:
        e = sel_d[ag]; e = e < 0 ? 0 : (e > 7 ? 7 : e);
        src = Wd2 + (size_t)e * 65536;  oq = w4 + (size_t)ag * 65536;
        n4 = 16384; break;
    default:
        src = inputs + (size_t)ag * 524288; oq = inq + (size_t)ag * 524288;
        n4 = 131072; break;
    }
    for (int i = blockIdx.x * 256 + threadIdx.x; i < n4; i += 64 * 256) {
        float4 v = ((const float4*)src)[i];
        ((uint2*)oq)[i] = make_uint2(pack2h(v.x, v.y), pack2h(v.z, v.w));
    }
}

// ---------------- main GEMM ------------------------------------------------
// CTA tile 128m x 128n, 8 warps (4m x 2n, warp tile 32m x 64n), BK=64,
// 3-stage cp.async, FULLY UNROLLED over NC chunks (compile-time stage
// offsets). Stage: A 16KB | B 16KB = 32KB. Single fp16 MMA pass.
// OMODE: 0 = fp32 out + bias, 1 = fp16 out + bias, 2 = raw fp32 partial.
template <int K, int KROW, int N, bool RELU, int OMODE>
__global__ void __launch_bounds__(256, 2)
gemm_mma_kernel(const f16* __restrict__ A_,
                const f16* __restrict__ W_,
                const float* __restrict__ Ball,
                float* __restrict__ Out,
                f16* __restrict__ Oq,
                const int* __restrict__ sel)
{
    extern __shared__ __align__(1024) char smem[];
    const uint32_t sb = smem_u32(smem);

    const int tid  = threadIdx.x;
    const int wid  = tid >> 5;
    const int lane = tid & 31;

    const int ag = blockIdx.z;
    int e = sel[ag]; e = e < 0 ? 0 : (e > 7 ? 7 : e);

    const int NX = N / 128;
    const int kg = blockIdx.x / NX;
    const int bn = (blockIdx.x % NX) * 128;
    const int bm = blockIdx.y * 128;

    const f16* Ap = A_ + (size_t)ag * BATCH * KROW + (size_t)kg * K;
    const f16* Bp = W_ + (size_t)ag * KROW * N + (size_t)kg * K * N;
    const float* bp = Ball + (size_t)e * N;

    if (OMODE != 2 && tid < 128) ((float*)smem)[tid] = bp[bn + tid];

    const int m0 = (wid >> 1) * 32;
    const int n0 = (wid & 1) * 64;

    const int lrow = lane & 15, lqh = lane >> 4;
    uint32_t aA[2];
#pragma unroll
    for (int mt = 0; mt < 2; mt++) {
        int r = m0 + mt * 16 + lrow;
        aA[mt] = sb + 1024 + (uint32_t)(r * 128 + ((lqh ^ (r & 7)) << 4));
    }
    const int kr = (lane & 7) + ((lane >> 3) & 1) * 8;
    uint32_t bB[4];
#pragma unroll
    for (int g = 0; g < 4; g++) {
        int nch = ((n0 + g * 16) >> 3) + (lane >> 4);
        bB[g] = sb + 1024 + 16384 + (uint32_t)(kr * 256 + ((nch ^ (kr & 7)) << 4));
    }

    float acc[2][8][4];
#pragma unroll
    for (int mt = 0; mt < 2; mt++)
#pragma unroll
        for (int nt = 0; nt < 8; nt++)
#pragma unroll
            for (int j = 0; j < 4; j++) acc[mt][nt][j] = 0.0f;

    constexpr int NC = K / 64;

    auto ISSUE = [&](int c, uint32_t stg) {
        const int k0 = c * 64;
        const uint32_t s = sb + 1024 + stg;
#pragma unroll
        for (int i = 0; i < 4; i++) {
            int fid = i * 256 + tid;
            int r = fid >> 3, cq = fid & 7;
            size_t go = (size_t)(bm + r) * KROW + k0 + cq * 8;
            cp16(s + (uint32_t)(r * 128 + ((cq ^ (r & 7)) << 4)), Ap + go);
        }
#pragma unroll
        for (int i = 0; i < 4; i++) {
            int fid = i * 256 + tid;
            int r = fid >> 4, cq = fid & 15;
            size_t go = (size_t)(k0 + r) * N + bn + cq * 8;
            cp16(s + 16384 + (uint32_t)(r * 256 + ((cq ^ (r & 7)) << 4)), Bp + go);
        }
        CP_COMMIT();
    };

    ISSUE(0, 0);
    ISSUE(1, 32768);

    // ---- fully unrolled mainloop: compile-time stage offsets ----
#pragma unroll
    for (int c = 0; c < NC; c++) {
        if (c + 1 < NC) cp_wait<1>(); else cp_wait<0>();
        __syncthreads();
        if (c + 2 < NC) ISSUE(c + 2, (uint32_t)((c + 2) % 3) * 32768u);

        const uint32_t stg = (uint32_t)(c % 3) * 32768u;   // immediate after unroll
#pragma unroll
        for (int ks = 0; ks < 4; ks++) {
            uint32_t ah[2][4];
#pragma unroll
            for (int mt = 0; mt < 2; mt++)
                ldsm4(ah[mt], (aA[mt] + stg) ^ ((uint32_t)ks << 5));
#pragma unroll
            for (int g = 0; g < 4; g++) {
                uint32_t b[4];
                ldsm4t(b, bB[g] + stg + (uint32_t)ks * 4096u);
#pragma unroll
                for (int mt = 0; mt < 2; mt++) {
                    const int nt = g * 2;
                    mma_f16(acc[mt][nt],     ah[mt], b[0], b[1]);
                    mma_f16(acc[mt][nt + 1], ah[mt], b[2], b[3]);
                }
            }
        }
    }

    // ---- epilogue ----
    const float* bias = (const float*)smem;
    float* Cp  = (OMODE == 0) ? (Out + (size_t)ag * BATCH * N) : nullptr;
    float* Pp  = (OMODE == 2) ? (Out + ((size_t)kg * NUM_AGENTS + ag) * BATCH * N) : nullptr;
    f16*   OqP = (OMODE == 1) ? (Oq + (size_t)ag * BATCH * N) : nullptr;

#pragma unroll
    for (int mt = 0; mt < 2; mt++) {
        const int mrow = bm + m0 + mt * 16 + (lane >> 2);
#pragma unroll
        for (int nt = 0; nt < 8; nt++) {
            const int nc = n0 + nt * 8 + 2 * (lane & 3);
            float o0 = acc[mt][nt][0], o1 = acc[mt][nt][1];
            float o2 = acc[mt][nt][2], o3 = acc[mt][nt][3];
            if (OMODE != 2) {
                const float b0 = bias[nc], b1 = bias[nc + 1];
                o0 += b0; o1 += b1; o2 += b0; o3 += b1;
            }
            if (RELU) {
                o0 = fmaxf(o0, 0.f); o1 = fmaxf(o1, 0.f);
                o2 = fmaxf(o2, 0.f); o3 = fmaxf(o3, 0.f);
            }
            const size_t i0 = (size_t)mrow * N + bn + nc;
            const size_t i1 = (size_t)(mrow + 8) * N + bn + nc;
            if (OMODE == 1) {
                *(uint32_t*)(OqP + i0) = pack2h(o0, o1);
                *(uint32_t*)(OqP + i1) = pack2h(o2, o3);
            } else if (OMODE == 0) {
                *(float2*)(Cp + i0) = make_float2(o0, o1);
                *(float2*)(Cp + i1) = make_float2(o2, o3);
            } else {
                *(float2*)(Pp + i0) = make_float2(o0, o1);
                *(float2*)(Pp + i1) = make_float2(o2, o3);
            }
        }
    }
}

// ---------------- split-K reduce: out = p0 + p1 + bias ---------------------
__global__ void __launch_bounds__(256)
reduce4_kernel(const float* __restrict__ P, const float* __restrict__ Ball,
               const int* __restrict__ sel_d, float* __restrict__ out)
{
    const int i = blockIdx.x * 256 + threadIdx.x;          // float4 index
    const float4 a = ((const float4*)P)[i];
    const float4 b = ((const float4*)P)[i + 524288];
    const int e4 = i * 4;
    const int ag = e4 >> 18;                               // / (2048*128)
    int e = sel_d[ag]; e = e < 0 ? 0 : (e > 7 ? 7 : e);
    const float4 bb = *(const float4*)(Ball + e * 128 + (e4 & 127));
    ((float4*)out)[i] = make_float4(a.x + b.x + bb.x, a.y + b.y + bb.y,
                                    a.z + b.z + bb.z, a.w + b.w + bb.w);
}

// ---------------------------------------------------------------------------
extern "C" void kernel_launch(void* const* d_in, const int* in_sizes, int n_in,
                              void* d_out, int out_size)
{
    const float* inputs = (const float*)d_in[0];
    const int*   sel_s  = (const int*)d_in[1];
    const int*   sel_d  = (const int*)d_in[2];
    const float* Ws1 = (const float*)d_in[3];
    const float* bs1 = (const float*)d_in[4];
    const float* Ws2 = (const float*)d_in[5];
    const float* bs2 = (const float*)d_in[6];
    const float* Wd1 = (const float*)d_in[7];
    const float* bd1 = (const float*)d_in[8];
    const float* Wd2 = (const float*)d_in[9];
    const float* bd2 = (const float*)d_in[10];
    float* out = (float*)d_out;

    void* p;
    f16 *inq, *y1, *y2, *y3, *w1, *w2, *w3, *w4;
    float* p4;
    cudaGetSymbolAddress(&p, g_inq); inq = (f16*)p;
    cudaGetSymbolAddress(&p, g_y1);  y1  = (f16*)p;
    cudaGetSymbolAddress(&p, g_y2);  y2  = (f16*)p;
    cudaGetSymbolAddress(&p, g_y3);  y3  = (f16*)p;
    cudaGetSymbolAddress(&p, g_p4);  p4  = (float*)p;
    cudaGetSymbolAddress(&p, g_w1);  w1  = (f16*)p;
    cudaGetSymbolAddress(&p, g_w2);  w2  = (f16*)p;
    cudaGetSymbolAddress(&p, g_w3);  w3  = (f16*)p;
    cudaGetSymbolAddress(&p, g_w4);  w4  = (f16*)p;

    const int SMEM_BYTES = 1024 + 3 * 32768;   // 99328
    cudaFuncSetAttribute(gemm_mma_kernel<256, 256, 512, true,  1>,
                         cudaFuncAttributeMaxDynamicSharedMemorySize, SMEM_BYTES);
    cudaFuncSetAttribute(gemm_mma_kernel<512, 512, 256, true,  1>,
                         cudaFuncAttributeMaxDynamicSharedMemorySize, SMEM_BYTES);
    cudaFuncSetAttribute(gemm_mma_kernel<256, 512, 128, false, 2>,
                         cudaFuncAttributeMaxDynamicSharedMemorySize, SMEM_BYTES);

    prep_kernel<<<dim3(64, 5, 8), 256>>>(Ws1, Ws2, Wd1, Wd2, inputs, sel_s, sel_d,
                                         w1, w2, w3, w4, inq);

    dim3 blk(256);
    gemm_mma_kernel<256, 256, 512, true,  1><<<dim3(4, 16, 8), blk, SMEM_BYTES>>>(
        inq, w1, bs1, nullptr, y1, sel_s);
    gemm_mma_kernel<512, 512, 256, true,  1><<<dim3(2, 16, 8), blk, SMEM_BYTES>>>(
        y1, w2, bs2, nullptr, y2, sel_s);
    gemm_mma_kernel<256, 256, 512, true,  1><<<dim3(4, 16, 8), blk, SMEM_BYTES>>>(
        y2, w3, bd1, nullptr, y3, sel_d);
    // L4: split-K x2 -> raw partials, then deterministic reduce (+bias)
    gemm_mma_kernel<256, 512, 128, false, 2><<<dim3(2, 16, 8), blk, SMEM_BYTES>>>(
        y3, w4, bd2, p4, nullptr, sel_d);
    reduce4_kernel<<<2048, 256>>>(p4, bd2, sel_d, out);
}